// round 7
// baseline (speedup 1.0000x reference)
#include <cuda_runtime.h>
#include <cuda_fp16.h>
#include <cstdint>

#define B_    32
#define M_    512
#define S_    10
#define V_    32000
#define D_    128

#define GBLK  2048            // gather blocks: 512 thr, 8 m per block, 2 warps/m
#define GPB   64              // gather blocks per batch
#define FSPL  16              // m-splits per batch in k_F12 -> 512 blocks
#define FBLK  (B_ * FSPL)

// Bags for tables 1..3 in fp16, packed 4 dims per uint2.
__device__ __align__(16) uint2 g_bagh[3u * B_ * M_ * (D_ / 4)];   // 12.6 MB
__device__ __align__(16) float g_part0[GBLK * D_];     // hop-0 partials
__device__ float g_den0[GBLK];
__device__ __align__(16) float g_partF[FBLK * D_];     // hop-1 partials
__device__ float g_denF[FBLK];
__device__ __align__(16) float g_part2[FBLK * D_];     // hop-2 partials
__device__ float g_den2[FBLK];
__device__ unsigned int g_tick;                        // monotonic grid-barrier ticket

__device__ __forceinline__ float warpSum(float v) {
    #pragma unroll
    for (int o = 16; o > 0; o >>= 1) v += __shfl_xor_sync(0xffffffffu, v, o);
    return v;
}
__device__ __forceinline__ uint2 pack4(float4 v) {
    __half2 lo = __floats2half2_rn(v.x, v.y);
    __half2 hi = __floats2half2_rn(v.z, v.w);
    uint2 r;
    r.x = *reinterpret_cast<unsigned*>(&lo);
    r.y = *reinterpret_cast<unsigned*>(&hi);
    return r;
}
__device__ __forceinline__ float4 unpack4(uint2 p) {
    __half2 lo = *reinterpret_cast<__half2*>(&p.x);
    __half2 hi = *reinterpret_cast<__half2*>(&p.y);
    float2 l = __half22float2(lo);
    float2 h = __half22float2(hi);
    return make_float4(l.x, l.y, h.x, h.y);
}

// Ticket grid barrier (monotonic, replay-safe). Requires all FBLK blocks
// co-resident (512 blocks << capacity at <=64 regs / 5KB smem).
__device__ __forceinline__ void gridbar()
{
    __threadfence();
    __syncthreads();
    if (threadIdx.x == 0) {
        const unsigned arrive = atomicAdd(&g_tick, 1u) + 1u;
        const unsigned target = ((arrive + FBLK - 1u) / FBLK) * FBLK;
        while (*((volatile unsigned*)&g_tick) < target) __nanosleep(32);
    }
    __syncthreads();
    __threadfence();
}

// ---------------------------------------------------------------------------
// Gather: TWO warps per (b,m). X-warp (wid 0..7): tables C0,C1 — hop-0 dot,
// exp, partial combine, bag-C1 store. Y-warp (wid 8..15): tables C2,C3 stores.
// 512 thr, <=42 regs (launch_bounds) -> 3 blocks/SM = 48 warps = 75% occ.
// ---------------------------------------------------------------------------
__global__ void __launch_bounds__(512, 3) k_gather(const int* __restrict__ story,
                                                   const float* __restrict__ hidden,
                                                   const float* __restrict__ C)
{
    __shared__ __align__(16) float s_pt[8][D_];
    __shared__ float s_den[8];

    const int tid  = threadIdx.x;
    const int lane = tid & 31;
    const int wid  = tid >> 5;          // 0..15
    const bool isX = (wid < 8);
    const int  ml  = wid & 7;           // m-local 0..7
    const int  g   = blockIdx.x * 8 + ml;
    const int  b   = g >> 9;            // / M_
    const int  m   = g & (M_ - 1);

    int tok = 0;
    if (lane < S_) tok = story[((size_t)b * M_ + m) * S_ + lane];

    const float4* C4 = reinterpret_cast<const float4*>(C);
    const size_t tabstr = (size_t)V_ * (D_ / 4);
    const float4* base0 = C4 + (isX ? 0 : 2) * tabstr;   // C0 or C2

    float4 a0 = make_float4(0.f, 0.f, 0.f, 0.f);
    float4 a1 = a0;

    #pragma unroll
    for (int s = 0; s < S_; s++) {
        const int t = __shfl_sync(0xffffffffu, tok, s);
        const size_t idx = (size_t)t * (D_ / 4) + lane;
        const float4 r0 = base0[idx];
        const float4 r1 = base0[idx + tabstr];
        a0.x += r0.x; a0.y += r0.y; a0.z += r0.z; a0.w += r0.w;
        a1.x += r1.x; a1.y += r1.y; a1.z += r1.z; a1.w += r1.w;
    }

    const size_t row  = ((size_t)b * M_ + m) * (D_ / 4) + lane;
    const size_t bstr = (size_t)B_ * M_ * (D_ / 4);

    if (isX) {
        // hop-0: logit0 = a0(C0-bag)·u0, e = exp, partial = e*a1(C1-bag)
        const float4 u4 = reinterpret_cast<const float4*>(hidden + (size_t)b * D_)[lane];
        float d = a0.x * u4.x + a0.y * u4.y + a0.z * u4.z + a0.w * u4.w;
        d = warpSum(d);
        const float e = __expf(d);
        reinterpret_cast<float4*>(&s_pt[ml][0])[lane] =
            make_float4(e * a1.x, e * a1.y, e * a1.z, e * a1.w);
        if (lane == 0) s_den[ml] = e;
        g_bagh[row] = pack4(a1);                 // table C1
    } else {
        g_bagh[row + bstr]     = pack4(a0);      // table C2
        g_bagh[row + 2 * bstr] = pack4(a1);      // table C3
    }

    __syncthreads();
    if (tid < D_) {
        float v = 0.f;
        #pragma unroll
        for (int k = 0; k < 8; k++) v += s_pt[k][tid];
        g_part0[(size_t)blockIdx.x * D_ + tid] = v;
    }
    if (tid == 0) {
        float dn = 0.f;
        #pragma unroll
        for (int k = 0; k < 8; k++) dn += s_den[k];
        g_den0[blockIdx.x] = dn;
    }
}

// ---------------------------------------------------------------------------
// k_F12: hops 1 and 2 in one kernel (512 blocks, single wave, grid barriers).
//   u1 (redundant reduce of gather partials) -> hop-1 pass -> partials
//   gridbar -> u2 (redundant reduce) -> hop-2 pass (logits -> OUT) -> partials
//   gridbar -> sp==0 blocks reduce -> final u3 -> OUT
// ---------------------------------------------------------------------------
__global__ void __launch_bounds__(256) k_F12(const float* __restrict__ hidden,
                                             float* __restrict__ out)
{
    __shared__ __align__(16) float s_u[D_];
    __shared__ __align__(16) float s_pt[8][D_];
    __shared__ float s_den[8];

    const int blk  = blockIdx.x;
    const int b    = blk / FSPL;
    const int sp   = blk % FSPL;
    const int tid  = threadIdx.x;
    const int lane = tid & 31;
    const int wid  = tid >> 5;

    const size_t bstr  = (size_t)B_ * M_ * (D_ / 4);
    const size_t rbase = (size_t)(b * M_ + sp * 32) * (D_ / 4) + lane;

    // ---- u1 = hidden + (Σ num0)/(Σ den0), redundant per block ----
    if (tid < D_) {
        float dn = 0.f;
        #pragma unroll 8
        for (int k = 0; k < GPB; k++) dn += g_den0[b * GPB + k];
        float num = 0.f;
        #pragma unroll 8
        for (int k = 0; k < GPB; k++) num += g_part0[((size_t)b * GPB + k) * D_ + tid];
        s_u[tid] = hidden[(size_t)b * D_ + tid] + num / dn;
    }
    __syncthreads();

    // ---- hop-1 pass over this block's 32 m (bags C1 -> logit, C2 -> num) ----
    {
        const float4 u4 = reinterpret_cast<const float4*>(s_u)[lane];
        float4 acc = make_float4(0.f, 0.f, 0.f, 0.f);
        float den = 0.f;
        #pragma unroll
        for (int i = 0; i < 4; i++) {
            const int ml = wid * 4 + i;
            const size_t r = rbase + (size_t)ml * (D_ / 4);
            const float4 va = unpack4(g_bagh[r]);               // C1
            const float4 vb = unpack4(g_bagh[bstr + r]);        // C2
            float d = va.x * u4.x + va.y * u4.y + va.z * u4.z + va.w * u4.w;
            d = warpSum(d);
            const float e = __expf(d);
            acc.x += e * vb.x; acc.y += e * vb.y;
            acc.z += e * vb.z; acc.w += e * vb.w;
            den += e;
        }
        reinterpret_cast<float4*>(&s_pt[wid][0])[lane] = acc;
        if (lane == 0) s_den[wid] = den;
    }
    __syncthreads();
    if (tid < D_) {
        float v = 0.f;
        #pragma unroll
        for (int k = 0; k < 8; k++) v += s_pt[k][tid];
        g_partF[(size_t)blk * D_ + tid] = v;
    }
    if (tid == 0) {
        float dn = 0.f;
        #pragma unroll
        for (int k = 0; k < 8; k++) dn += s_den[k];
        g_denF[blk] = dn;
    }

    gridbar();

    // ---- u2 = u1 + (Σ numF)/(Σ denF), redundant per block ----
    if (tid < D_) {
        float dn = 0.f;
        #pragma unroll
        for (int k = 0; k < FSPL; k++) dn += g_denF[b * FSPL + k];
        float num = 0.f;
        #pragma unroll
        for (int k = 0; k < FSPL; k++) num += g_partF[((size_t)b * FSPL + k) * D_ + tid];
        s_u[tid] = s_u[tid] + num / dn;
    }
    __syncthreads();

    // ---- hop-2 pass: logits -> OUTPUT; partials for u3 (C2 -> logit, C3 -> num) ----
    {
        const float4 u4 = reinterpret_cast<const float4*>(s_u)[lane];
        float4 acc = make_float4(0.f, 0.f, 0.f, 0.f);
        float den = 0.f;
        #pragma unroll
        for (int i = 0; i < 4; i++) {
            const int ml = wid * 4 + i;
            const size_t r = rbase + (size_t)ml * (D_ / 4);
            const float4 va = unpack4(g_bagh[bstr + r]);        // C2
            const float4 vb = unpack4(g_bagh[2 * bstr + r]);    // C3
            float d = va.x * u4.x + va.y * u4.y + va.z * u4.z + va.w * u4.w;
            d = warpSum(d);
            const float e = __expf(d);
            if (lane == 0) out[(size_t)b * M_ + sp * 32 + ml] = d;  // prob_logit
            acc.x += e * vb.x; acc.y += e * vb.y;
            acc.z += e * vb.z; acc.w += e * vb.w;
            den += e;
        }
        reinterpret_cast<float4*>(&s_pt[wid][0])[lane] = acc;
        if (lane == 0) s_den[wid] = den;
    }
    __syncthreads();
    if (tid < D_) {
        float v = 0.f;
        #pragma unroll
        for (int k = 0; k < 8; k++) v += s_pt[k][tid];
        g_part2[(size_t)blk * D_ + tid] = v;
    }
    if (tid == 0) {
        float dn = 0.f;
        #pragma unroll
        for (int k = 0; k < 8; k++) dn += s_den[k];
        g_den2[blk] = dn;
    }

    gridbar();

    // ---- final: u3 -> OUTPUT (one block per batch) ----
    if (sp == 0 && tid < D_) {
        float dn = 0.f;
        #pragma unroll
        for (int k = 0; k < FSPL; k++) dn += g_den2[b * FSPL + k];
        float num = 0.f;
        #pragma unroll
        for (int k = 0; k < FSPL; k++) num += g_part2[((size_t)b * FSPL + k) * D_ + tid];
        out[(size_t)B_ * M_ + (size_t)b * D_ + tid] = s_u[tid] + num / dn;
    }
}

extern "C" void kernel_launch(void* const* d_in, const int* in_sizes, int n_in,
                              void* d_out, int out_size)
{
    const int*   story  = (const int*)  d_in[0];   // [B, M, S] int32
    const float* hidden = (const float*)d_in[1];   // [B, 1, D] f32
    const float* C      = (const float*)d_in[2];   // [4, V, D] f32
    float* out = (float*)d_out;                    // [B*M] logits ++ [B*D] u

    k_gather<<<GBLK, 512>>>(story, hidden, C);     // hop-0 fused, 2 warps/(b,m)
    k_F12   <<<FBLK, 256>>>(hidden, out);          // hops 1+2, grid-barriered
}

// round 8
// speedup vs baseline: 1.1000x; 1.1000x over previous
#include <cuda_runtime.h>
#include <cuda_fp16.h>
#include <cstdint>

#define B_    32
#define M_    512
#define S_    10
#define V_    32000
#define D_    128

#define GBLK  2048            // gather blocks: 512 thr, 8 m per block, 2 warps/m
#define GPB   64              // gather blocks per batch (hop-0 partials per batch)
#define FSPL  16              // m-splits per batch in k_F -> 512 blocks, 32 m/block

// Bags for tables 1..3 in fp16, packed 4 dims per uint2.
__device__ __align__(16) uint2 g_bagh[3u * B_ * M_ * (D_ / 4)];   // 12.6 MB
__device__ __align__(16) float g_part0[GBLK * D_];     // hop-0 partials (gather)
__device__ float g_den0[GBLK];
__device__ __align__(16) float g_partF[B_ * FSPL * D_]; // hop partials (k_F)
__device__ float g_denF[B_ * FSPL];
__device__ __align__(16) float g_u[B_ * D_];           // u1 (published by k_F1)
__device__ unsigned int g_cnt[B_];                     // k_F2 arrival counters (self-reset)

__device__ __forceinline__ float warpSum(float v) {
    #pragma unroll
    for (int o = 16; o > 0; o >>= 1) v += __shfl_xor_sync(0xffffffffu, v, o);
    return v;
}
__device__ __forceinline__ uint2 pack4(float4 v) {
    __half2 lo = __floats2half2_rn(v.x, v.y);
    __half2 hi = __floats2half2_rn(v.z, v.w);
    uint2 r;
    r.x = *reinterpret_cast<unsigned*>(&lo);
    r.y = *reinterpret_cast<unsigned*>(&hi);
    return r;
}
__device__ __forceinline__ float4 unpack4(uint2 p) {
    __half2 lo = *reinterpret_cast<__half2*>(&p.x);
    __half2 hi = *reinterpret_cast<__half2*>(&p.y);
    float2 l = __half22float2(lo);
    float2 h = __half22float2(hi);
    return make_float4(l.x, l.y, h.x, h.y);
}

// ---------------------------------------------------------------------------
// Gather (R7 shape, the proven winner): TWO warps per (b,m).
// X-warp (wid 0..7): tables C0,C1 — hop-0 dot, exp, partial, bag-C1 store.
// Y-warp (wid 8..15): tables C2,C3 bag stores.
// 512 thr, __launch_bounds__(512,3) -> 48 warps/SM (75% occ).
// ---------------------------------------------------------------------------
__global__ void __launch_bounds__(512, 3) k_gather(const int* __restrict__ story,
                                                   const float* __restrict__ hidden,
                                                   const float* __restrict__ C)
{
    __shared__ __align__(16) float s_pt[8][D_];
    __shared__ float s_den[8];

    const int tid  = threadIdx.x;
    const int lane = tid & 31;
    const int wid  = tid >> 5;          // 0..15
    const bool isX = (wid < 8);
    const int  ml  = wid & 7;           // m-local 0..7
    const int  g   = blockIdx.x * 8 + ml;
    const int  b   = g >> 9;            // / M_
    const int  m   = g & (M_ - 1);

    int tok = 0;
    if (lane < S_) tok = story[((size_t)b * M_ + m) * S_ + lane];

    const float4* C4 = reinterpret_cast<const float4*>(C);
    const size_t tabstr = (size_t)V_ * (D_ / 4);
    const float4* base0 = C4 + (isX ? 0 : 2) * tabstr;   // C0 or C2

    float4 a0 = make_float4(0.f, 0.f, 0.f, 0.f);
    float4 a1 = a0;

    #pragma unroll
    for (int s = 0; s < S_; s++) {
        const int t = __shfl_sync(0xffffffffu, tok, s);
        const size_t idx = (size_t)t * (D_ / 4) + lane;
        const float4 r0 = base0[idx];
        const float4 r1 = base0[idx + tabstr];
        a0.x += r0.x; a0.y += r0.y; a0.z += r0.z; a0.w += r0.w;
        a1.x += r1.x; a1.y += r1.y; a1.z += r1.z; a1.w += r1.w;
    }

    const size_t row  = ((size_t)b * M_ + m) * (D_ / 4) + lane;
    const size_t bstr = (size_t)B_ * M_ * (D_ / 4);

    if (isX) {
        const float4 u4 = reinterpret_cast<const float4*>(hidden + (size_t)b * D_)[lane];
        float d = a0.x * u4.x + a0.y * u4.y + a0.z * u4.z + a0.w * u4.w;
        d = warpSum(d);
        const float e = __expf(d);
        reinterpret_cast<float4*>(&s_pt[ml][0])[lane] =
            make_float4(e * a1.x, e * a1.y, e * a1.z, e * a1.w);
        if (lane == 0) s_den[ml] = e;
        g_bagh[row] = pack4(a1);                 // table C1
    } else {
        g_bagh[row + bstr]     = pack4(a0);      // table C2
        g_bagh[row + 2 * bstr] = pack4(a1);      // table C3
    }

    __syncthreads();
    if (tid < D_) {
        float v = 0.f;
        #pragma unroll
        for (int k = 0; k < 8; k++) v += s_pt[k][tid];
        g_part0[(size_t)blockIdx.x * D_ + tid] = v;
    }
    if (tid == 0) {
        float dn = 0.f;
        #pragma unroll
        for (int k = 0; k < 8; k++) dn += s_den[k];
        g_den0[blockIdx.x] = dn;
    }
}

// ---------------------------------------------------------------------------
// k_F1: redundantly reduce gather partials -> u1 (SMEM, two-level: 2 threads
// per dim x 32 partials each); run hop-1 pass; write hop-1 partials.
// sp==0 block publishes u1 to g_u.
// ---------------------------------------------------------------------------
__global__ void __launch_bounds__(256) k_F1(const float* __restrict__ hidden)
{
    __shared__ __align__(16) float s_u[D_];
    __shared__ __align__(16) float s_n[2][D_];
    __shared__ float s_dn[2];
    __shared__ __align__(16) float s_pt[8][D_];
    __shared__ float s_den[8];

    const int blk  = blockIdx.x;
    const int b    = blk / FSPL;
    const int sp   = blk % FSPL;
    const int tid  = threadIdx.x;
    const int lane = tid & 31;
    const int wid  = tid >> 5;

    // ---- u1 reduce, 2-level: dim = tid&127, half = tid>>7 handles 32 partials
    {
        const int dim  = tid & 127;
        const int half = tid >> 7;
        const int k0   = half * 32;
        float dn = 0.f, num = 0.f;
        #pragma unroll 8
        for (int k = k0; k < k0 + 32; k++) {
            dn  += g_den0[b * GPB + k];
            num += g_part0[((size_t)b * GPB + k) * D_ + dim];
        }
        s_n[half][dim] = num;
        if (dim == 0) s_dn[half] = dn;
    }
    __syncthreads();
    if (tid < D_) {
        s_u[tid] = hidden[(size_t)b * D_ + tid]
                 + (s_n[0][tid] + s_n[1][tid]) / (s_dn[0] + s_dn[1]);
        if (sp == 0) g_u[(size_t)b * D_ + tid] = s_u[tid];
    }
    __syncthreads();

    // ---- hop-1 pass over this block's 32 m (C1 -> logit, C2 -> num) ----
    const float4 u4 = reinterpret_cast<const float4*>(s_u)[lane];
    const size_t bstr  = (size_t)B_ * M_ * (D_ / 4);
    const size_t rbase = (size_t)(b * M_ + sp * 32) * (D_ / 4) + lane;

    float4 acc = make_float4(0.f, 0.f, 0.f, 0.f);
    float den = 0.f;
    #pragma unroll
    for (int i = 0; i < 4; i++) {
        const int ml = wid * 4 + i;
        const size_t r = rbase + (size_t)ml * (D_ / 4);
        const float4 va = unpack4(g_bagh[r]);               // C1
        const float4 vb = unpack4(g_bagh[bstr + r]);        // C2
        float d = va.x * u4.x + va.y * u4.y + va.z * u4.z + va.w * u4.w;
        d = warpSum(d);
        const float e = __expf(d);
        acc.x += e * vb.x; acc.y += e * vb.y;
        acc.z += e * vb.z; acc.w += e * vb.w;
        den += e;
    }
    reinterpret_cast<float4*>(&s_pt[wid][0])[lane] = acc;
    if (lane == 0) s_den[wid] = den;
    __syncthreads();

    if (tid < D_) {
        float v = 0.f;
        #pragma unroll
        for (int k = 0; k < 8; k++) v += s_pt[k][tid];
        g_partF[(size_t)blk * D_ + tid] = v;
    }
    if (tid == 0) {
        float dn = 0.f;
        #pragma unroll
        for (int k = 0; k < 8; k++) dn += s_den[k];
        g_denF[blk] = dn;
    }
}

// ---------------------------------------------------------------------------
// k_F2: redundantly reduce hop-1 partials -> u2 (SMEM); run hop-2 pass
// (logits -> OUTPUT); last-arriving block per batch reduces hop-2 partials,
// writes final u3 to OUTPUT. Counter self-resets (replay-safe).
// ---------------------------------------------------------------------------
__global__ void __launch_bounds__(256) k_F2(float* __restrict__ out)
{
    __shared__ __align__(16) float s_u[D_];
    __shared__ __align__(16) float s_n[2][D_];
    __shared__ float s_dn[2];
    __shared__ __align__(16) float s_pt[8][D_];
    __shared__ float s_den[8];
    __shared__ int s_last;

    const int blk  = blockIdx.x;
    const int b    = blk / FSPL;
    const int sp   = blk % FSPL;
    const int tid  = threadIdx.x;
    const int lane = tid & 31;
    const int wid  = tid >> 5;

    // ---- u2 reduce, 2-level: 2 threads per dim x 8 partials each ----
    {
        const int dim  = tid & 127;
        const int half = tid >> 7;
        const int k0   = half * 8;
        float dn = 0.f, num = 0.f;
        #pragma unroll
        for (int k = k0; k < k0 + 8; k++) {
            dn  += g_denF[b * FSPL + k];
            num += g_partF[((size_t)b * FSPL + k) * D_ + dim];
        }
        s_n[half][dim] = num;
        if (dim == 0) s_dn[half] = dn;
    }
    __syncthreads();
    if (tid < D_) {
        s_u[tid] = g_u[(size_t)b * D_ + tid]
                 + (s_n[0][tid] + s_n[1][tid]) / (s_dn[0] + s_dn[1]);
    }
    __syncthreads();

    // ---- hop-2 pass: logits -> OUTPUT; partials for u3 (C2 -> logit, C3 -> num)
    const float4 u4 = reinterpret_cast<const float4*>(s_u)[lane];
    const size_t bstr  = (size_t)B_ * M_ * (D_ / 4);
    const size_t rbase = (size_t)(b * M_ + sp * 32) * (D_ / 4) + lane;

    float4 acc = make_float4(0.f, 0.f, 0.f, 0.f);
    float den = 0.f;
    #pragma unroll
    for (int i = 0; i < 4; i++) {
        const int ml = wid * 4 + i;
        const size_t r = rbase + (size_t)ml * (D_ / 4);
        const float4 va = unpack4(g_bagh[bstr + r]);        // C2
        const float4 vb = unpack4(g_bagh[2 * bstr + r]);    // C3
        float d = va.x * u4.x + va.y * u4.y + va.z * u4.z + va.w * u4.w;
        d = warpSum(d);
        const float e = __expf(d);
        if (lane == 0) out[(size_t)b * M_ + sp * 32 + ml] = d;  // prob_logit
        acc.x += e * vb.x; acc.y += e * vb.y;
        acc.z += e * vb.z; acc.w += e * vb.w;
        den += e;
    }
    reinterpret_cast<float4*>(&s_pt[wid][0])[lane] = acc;
    if (lane == 0) s_den[wid] = den;
    __syncthreads();

    if (tid < D_) {
        float v = 0.f;
        #pragma unroll
        for (int k = 0; k < 8; k++) v += s_pt[k][tid];
        g_partF[(size_t)blk * D_ + tid] = v;     // reuse partF for hop-2
    }
    if (tid == 0) {
        float dn = 0.f;
        #pragma unroll
        for (int k = 0; k < 8; k++) dn += s_den[k];
        g_denF[blk] = dn;
    }
    __syncthreads();

    // ---- last-block-per-batch: u3 -> OUTPUT ----
    if (tid == 0) {
        __threadfence();
        const unsigned old = atomicAdd(&g_cnt[b], 1u);
        s_last = (old == FSPL - 1);
    }
    __syncthreads();
    if (s_last) {
        __threadfence();   // acquire peers' partial writes
        if (tid < D_) {
            float dn = 0.f;
            #pragma unroll
            for (int k = 0; k < FSPL; k++) dn += g_denF[b * FSPL + k];
            float num = 0.f;
            #pragma unroll
            for (int k = 0; k < FSPL; k++) num += g_partF[((size_t)b * FSPL + k) * D_ + tid];
            out[(size_t)B_ * M_ + (size_t)b * D_ + tid] = s_u[tid] + num / dn;
        }
        if (tid == 0) g_cnt[b] = 0;   // reset for next replay
    }
}

extern "C" void kernel_launch(void* const* d_in, const int* in_sizes, int n_in,
                              void* d_out, int out_size)
{
    const int*   story  = (const int*)  d_in[0];   // [B, M, S] int32
    const float* hidden = (const float*)d_in[1];   // [B, 1, D] f32
    const float* C      = (const float*)d_in[2];   // [4, V, D] f32
    float* out = (float*)d_out;                    // [B*M] logits ++ [B*D] u

    k_gather<<<GBLK, 512>>>(story, hidden, C);     // hop-0 fused, 2 warps/(b,m)
    k_F1    <<<B_ * FSPL, 256>>>(hidden);          // u1 + hop-1 pass
    k_F2    <<<B_ * FSPL, 256>>>(out);             // u2 + hop-2 + final u3
}